// round 5
// baseline (speedup 1.0000x reference)
#include <cuda_runtime.h>

#define NPAPER 100000
#define NAUTH  50000
#define NINST  5000
#define NTOT   155000
#define SRCROWS 305000
#define ETOT   900000

// ---------------- device scratch (no allocations allowed) ----------------
__device__ __align__(256) float g_X[(size_t)NTOT*128];   // current layer input features
__device__ __align__(256) float g_Y[(size_t)NTOT*128];   // layer output features
__device__ __align__(256) float g_K[(size_t)NTOT*128];
__device__ __align__(256) float g_Q[(size_t)NTOT*128];
__device__ __align__(256) float g_V[(size_t)NTOT*128];
__device__ __align__(256) float g_KR[(size_t)SRCROWS*128]; // per-edge-type relation-transformed K
__device__ __align__(256) float g_VR[(size_t)SRCROWS*128];
__device__ __align__(256) float g_SC[(size_t)ETOT*8];     // per edge-head scores / exp
__device__ __align__(256) float g_M[(size_t)NTOT*8];      // segment max
__device__ __align__(256) float g_DEN[(size_t)NTOT*8];    // segment expsum
__device__ __align__(256) float g_AGG[(size_t)NTOT*128];  // aggregated messages
__device__ int g_flags[3];  // [0]=swap{ei0,ei1}, [1]=swap{ei3,ei4}, [2]=layout (1 = [E,2] interleaved)

// ---------------- kernels ----------------

// Resolve edge-tensor layout ([2,E] vs interleaved [E,2]) and same-size pair order.
// t01 = first 500000-elem tensor, t34a/t34b = the two 200000-elem tensors.
__global__ void resolve_kernel(const int* __restrict__ t01,
                               const int* __restrict__ t34a,
                               const int* __restrict__ t34b)
{
    __shared__ int s[8];  // 0:a_h1 1:a_h2 2:a_odd 3:b_h1 4:b_h2 5:b_odd 6:c_h1 7:c_even
    if (threadIdx.x < 8) s[threadIdx.x] = 0;
    __syncthreads();
    int ah1 = 0, ah2 = 0, aodd = 0, bh1 = 0, bh2 = 0, bodd = 0, ch1 = 0, cev = 0;
    for (int i = threadIdx.x; i < 200000; i += blockDim.x) {
        int va = t34a[i], vb = t34b[i];
        if (i < 100000) { ah1 = max(ah1, va); bh1 = max(bh1, vb); }
        else            { ah2 = max(ah2, va); bh2 = max(bh2, vb); }
        if (i & 1) { aodd = max(aodd, va); bodd = max(bodd, vb); }
    }
    for (int i = threadIdx.x; i < 500000; i += blockDim.x) {
        int vc = t01[i];
        if (i < 250000) ch1 = max(ch1, vc);
        if (!(i & 1))   cev = max(cev, vc);
    }
    atomicMax(&s[0], ah1); atomicMax(&s[1], ah2); atomicMax(&s[2], aodd);
    atomicMax(&s[3], bh1); atomicMax(&s[4], bh2); atomicMax(&s[5], bodd);
    atomicMax(&s[6], ch1); atomicMax(&s[7], cev);
    __syncthreads();
    if (threadIdx.x == 0) {
        // [2,E]: ei3's dst half (inst <5000) or ei4's src half is small.
        // [E,2]: every half of both tensors contains author ids (~49999).
        int m4 = min(min(s[0], s[1]), min(s[3], s[4]));
        int layE2 = (m4 >= 10000) ? 1 : 0;
        g_flags[2] = layE2;
        // T(eptr3) is ei4 (inst->author, dst author) iff its dst-side max >= 10000
        g_flags[1] = layE2 ? ((s[2] >= 10000) ? 1 : 0)   // odd positions = dst
                           : ((s[1] >= 10000) ? 1 : 0);  // second half   = dst
        // T(eptr0) is ei1 (paper src) iff src-side max >= 60000
        int srcmax = layE2 ? s[7] : s[6];
        g_flags[0] = (srcmax >= 60000) ? 1 : 0;
    }
}

__global__ void init_kernel(float* __restrict__ M, float* __restrict__ D,
                            float* __restrict__ A, int nMH, int nA) {
    int i = blockIdx.x * blockDim.x + threadIdx.x;
    if (i < nMH) { M[i] = __int_as_float((int)0xFF800000); D[i] = 0.f; }
    if (i < nA)  A[i] = 0.f;
}

__device__ __forceinline__ float gelu_f(float x) {
    return 0.5f * x * (1.f + erff(x * 0.70710678118654752f));
}

__device__ __forceinline__ int edge_src(const int* b, int e, int E, int lay) {
    return lay ? b[2 * e] : b[e];
}
__device__ __forceinline__ int edge_dst(const int* b, int e, int E, int lay) {
    return lay ? b[2 * e + 1] : b[E + e];
}

// C[M,N] = epilogue(actA(A[M,K]) @ W[K,N] + bias), tile 64x64x16, 256 thr, 4x4 microtile.
__global__ __launch_bounds__(256)
void gemm_kernel(const float* __restrict__ A, int lda,
                 const float* __restrict__ W, int ldw,
                 const float* __restrict__ bias,
                 float* __restrict__ C, int ldc,
                 int M, int K, int geluA, int reluO,
                 const float* __restrict__ resid,
                 const float* __restrict__ skp)
{
    __shared__ float As[16][64];
    __shared__ float Ws[16][64];
    const int tid = threadIdx.x;
    const int tx = tid & 15, ty = tid >> 4;
    const int m0 = blockIdx.y * 64, n0 = blockIdx.x * 64;
    const int ar = tid >> 2, ac = (tid & 3) * 4;
    const int wr = tid >> 4, wn = (tid & 15) * 4;
    float acc[4][4];
#pragma unroll
    for (int i = 0; i < 4; i++)
#pragma unroll
        for (int j = 0; j < 4; j++) acc[i][j] = 0.f;

    for (int k0 = 0; k0 < K; k0 += 16) {
        float4 a4 = make_float4(0.f, 0.f, 0.f, 0.f);
        if (m0 + ar < M) a4 = *(const float4*)(A + (size_t)(m0 + ar) * lda + k0 + ac);
        if (geluA) { a4.x = gelu_f(a4.x); a4.y = gelu_f(a4.y);
                     a4.z = gelu_f(a4.z); a4.w = gelu_f(a4.w); }
        float4 w4 = *(const float4*)(W + (size_t)(k0 + wr) * ldw + n0 + wn);
        As[ac + 0][ar] = a4.x; As[ac + 1][ar] = a4.y;
        As[ac + 2][ar] = a4.z; As[ac + 3][ar] = a4.w;
        *(float4*)&Ws[wr][wn] = w4;
        __syncthreads();
#pragma unroll
        for (int k = 0; k < 16; k++) {
            float4 av = *(const float4*)&As[k][ty * 4];
            float4 wv = *(const float4*)&Ws[k][tx * 4];
            acc[0][0] += av.x * wv.x; acc[0][1] += av.x * wv.y; acc[0][2] += av.x * wv.z; acc[0][3] += av.x * wv.w;
            acc[1][0] += av.y * wv.x; acc[1][1] += av.y * wv.y; acc[1][2] += av.y * wv.z; acc[1][3] += av.y * wv.w;
            acc[2][0] += av.z * wv.x; acc[2][1] += av.z * wv.y; acc[2][2] += av.z * wv.z; acc[2][3] += av.z * wv.w;
            acc[3][0] += av.w * wv.x; acc[3][1] += av.w * wv.y; acc[3][2] += av.w * wv.z; acc[3][3] += av.w * wv.w;
        }
        __syncthreads();
    }
    float sa = 0.f;
    if (resid) { float s = *skp; sa = 1.f / (1.f + __expf(-s)); }
#pragma unroll
    for (int i = 0; i < 4; i++) {
        int m = m0 + ty * 4 + i;
        if (m < M) {
#pragma unroll
            for (int j = 0; j < 4; j++) {
                int n = n0 + tx * 4 + j;
                float v = acc[i][j] + bias[n];
                if (reluO) v = fmaxf(v, 0.f);
                if (resid) v = sa * v + (1.f - sa) * resid[(size_t)m * ldc + n];
                C[(size_t)m * ldc + n] = v;
            }
        }
    }
}

// Per-edge-type relation transform over all source nodes:
// KR[n,h,:] = Kin[n,h,:] @ krel[h] (16x16), same for V. fout = H*16.
__global__ __launch_bounds__(256)
void relx_kernel(const float* __restrict__ Kin, const float* __restrict__ Vin,
                 const float* __restrict__ krel, const float* __restrict__ vrel,
                 float* __restrict__ KR, float* __restrict__ VR, int nsrc, int H)
{
    extern __shared__ float sh[];
    float* skr = sh;
    float* svr = sh + H * 256;
    for (int i = threadIdx.x; i < H * 256; i += blockDim.x) {
        skr[i] = krel[i]; svr[i] = vrel[i];
    }
    __syncthreads();
    const int fout = H << 4;
    int tid = blockIdx.x * blockDim.x + threadIdx.x;
    if (tid >= nsrc * fout) return;
    int n = tid / fout, c = tid - n * fout;
    int h = c >> 4, eo = c & 15;
    const float* kin = Kin + (size_t)n * fout + h * 16;
    const float* vin = Vin + (size_t)n * fout + h * 16;
    const float* km = skr + h * 256 + eo;
    const float* vm = svr + h * 256 + eo;
    float ak = 0.f, av = 0.f;
#pragma unroll
    for (int d = 0; d < 16; d++) { ak += kin[d] * km[d << 4]; av += vin[d] * vm[d << 4]; }
    KR[tid] = ak; VR[tid] = av;
}

// sc[e,h] = dot(q[dst,h], kr[src,h]) * prel[h] / 4 ; atomicMax into M[dst,h]
__global__ __launch_bounds__(256)
void score_kernel(const int* __restrict__ ep0, const int* __restrict__ ep1,
                  const int* __restrict__ flagp, const int* __restrict__ layp,
                  const float* __restrict__ Q, const float* __restrict__ KR,
                  const float* __restrict__ prel, float* __restrict__ SC,
                  float* __restrict__ Mb, int E, int H, int ns, int nd)
{
    const int* base = (*flagp) ? ep1 : ep0;
    const int lay = *layp;
    int tid = blockIdx.x * blockDim.x + threadIdx.x;
    if (tid >= E * H) return;
    int e = tid / H, h = tid - e * H;
    int s = min(max(edge_src(base, e, E, lay), 0), ns - 1);
    int d = min(max(edge_dst(base, e, E, lay), 0), nd - 1);
    const float* q = Q + ((size_t)d * H + h) * 16;
    const float* k = KR + ((size_t)s * H + h) * 16;
    float sc = 0.f;
#pragma unroll
    for (int i = 0; i < 16; i++) sc += q[i] * k[i];
    sc *= prel[h] * 0.25f;
    SC[tid] = sc;
    float* mp = Mb + (size_t)d * H + h;
    if (sc >= 0.f) atomicMax((int*)mp, __float_as_int(sc));
    else           atomicMin((unsigned int*)mp, __float_as_uint(sc));
}

__global__ __launch_bounds__(256)
void expsum_kernel(const int* __restrict__ ep0, const int* __restrict__ ep1,
                   const int* __restrict__ flagp, const int* __restrict__ layp,
                   const float* __restrict__ Mb,
                   float* __restrict__ SC, float* __restrict__ Db,
                   int E, int H, int nd)
{
    const int* base = (*flagp) ? ep1 : ep0;
    const int lay = *layp;
    int tid = blockIdx.x * blockDim.x + threadIdx.x;
    if (tid >= E * H) return;
    int e = tid / H, h = tid - e * H;
    int d = min(max(edge_dst(base, e, E, lay), 0), nd - 1);
    float ex = __expf(SC[tid] - Mb[(size_t)d * H + h]);
    SC[tid] = ex;
    atomicAdd(Db + (size_t)d * H + h, ex);
}

// AGG[dst] += alpha * VR[src] ; one thread per (edge, 4 channels)
__global__ __launch_bounds__(256)
void agg_kernel(const int* __restrict__ ep0, const int* __restrict__ ep1,
                const int* __restrict__ flagp, const int* __restrict__ layp,
                const float* __restrict__ VR, const float* __restrict__ SC,
                const float* __restrict__ Db, float* __restrict__ AG,
                int E, int H, int ns, int nd)
{
    const int* base = (*flagp) ? ep1 : ep0;
    const int lay = *layp;
    const int f4 = H * 4;  // fout/4
    int tid = blockIdx.x * blockDim.x + threadIdx.x;
    if (tid >= E * f4) return;
    int e = tid / f4, c4 = tid - e * f4;
    int h = c4 >> 2;
    int s = min(max(edge_src(base, e, E, lay), 0), ns - 1);
    int d = min(max(edge_dst(base, e, E, lay), 0), nd - 1);
    float ex = SC[(size_t)e * H + h];
    float den = Db[(size_t)d * H + h];
    float alpha = ex / fmaxf(den, 1e-16f);
    const float4 v = *(const float4*)(VR + ((size_t)s * f4 + c4) * 4);
    float* p = AG + ((size_t)d * f4 + c4) * 4;
    atomicAdd(p + 0, v.x * alpha);
    atomicAdd(p + 1, v.y * alpha);
    atomicAdd(p + 2, v.z * alpha);
    atomicAdd(p + 3, v.w * alpha);
}

// ---------------- host orchestration ----------------

extern "C" void kernel_launch(void* const* d_in, const int* in_sizes, int n_in,
                              void* d_out, int out_size)
{
    static const long long ESIZE[30] = {
        25600000, 6400000, 320000,                      // x_paper, x_author, x_inst
        500000, 500000, 400000, 200000, 200000,         // ei0..ei4
        32768, 128, 16384, 128, 8192, 128,              // lin_w_p,b_p, w_a,b_a, w_i,b_i
        147456, 1152, 10240, 10240, 40, 49152, 384, 3,  // layer1 params
        73728, 576, 5120, 5120, 20, 12288, 192, 3       // layer2 params
    };
    const void* P[30];
    bool got[30];
    for (int j = 0; j < 30; j++) { got[j] = false; P[j] = nullptr; }
    for (int i = 0; i < n_in; i++) {
        for (int j = 0; j < 30; j++) {
            if (!got[j] && (long long)in_sizes[i] == ESIZE[j]) {
                P[j] = d_in[i]; got[j] = true; break;
            }
        }
    }
    for (int j = 0; j < 30; j++) if (!got[j]) return;   // unexpected input set

    const float* x_in[3]  = {(const float*)P[0], (const float*)P[1], (const float*)P[2]};
    const int*   eptr[5]  = {(const int*)P[3], (const int*)P[4], (const int*)P[5],
                             (const int*)P[6], (const int*)P[7]};
    const float* lin_w[3] = {(const float*)P[8], (const float*)P[10], (const float*)P[12]};
    const float* lin_b[3] = {(const float*)P[9], (const float*)P[11], (const float*)P[13]};
    const float* kqv_w[2] = {(const float*)P[14], (const float*)P[22]};
    const float* kqv_b[2] = {(const float*)P[15], (const float*)P[23]};
    const float* krel[2]  = {(const float*)P[16], (const float*)P[24]};
    const float* vrel[2]  = {(const float*)P[17], (const float*)P[25]};
    const float* prel[2]  = {(const float*)P[18], (const float*)P[26]};
    const float* outw[2]  = {(const float*)P[19], (const float*)P[27]};
    const float* outb[2]  = {(const float*)P[20], (const float*)P[28]};
    const float* skipv[2] = {(const float*)P[21], (const float*)P[29]};

    float *X, *Y, *Kb, *Qb, *Vb, *KR, *VR, *SCb, *Mb, *Db, *AG;
    int* FL;
#define GETSYM(p, s) do { if (cudaGetSymbolAddress((void**)&(p), s) != cudaSuccess) return; } while (0)
    GETSYM(X,  g_X);  GETSYM(Y,  g_Y);  GETSYM(Kb, g_K);  GETSYM(Qb, g_Q);
    GETSYM(Vb, g_V);  GETSYM(KR, g_KR); GETSYM(VR, g_VR); GETSYM(SCb, g_SC);
    GETSYM(Mb, g_M);  GETSYM(Db, g_DEN); GETSYM(AG, g_AGG); GETSYM(FL, g_flags);
#undef GETSYM

    const int ntyp[3]  = {NPAPER, NAUTH, NINST};
    const int roff[3]  = {0, NPAPER, NPAPER + NAUTH};
    const int idim[3]  = {256, 128, 64};
    // EDGE_TYPES = [(1,0), (0,0), (0,1), (1,2), (2,1)]
    const int esrc[5]  = {1, 0, 0, 1, 2};
    const int edst[5]  = {0, 0, 1, 2, 1};   // FIXED: e=3 dst=inst, e=4 dst=author
    const int ecnt[5]  = {250000, 250000, 200000, 100000, 100000};
    const int kroff[5] = {0, 50000, 150000, 250000, 300000};
    const int scoff[5] = {0, 250000, 500000, 700000, 800000};
    const int* epri[5]  = {eptr[0], eptr[1], eptr[2], eptr[3], eptr[4]};
    const int* ealt[5]  = {eptr[1], eptr[0], eptr[2], eptr[4], eptr[3]};
    const int* eflag[5] = {FL + 0, FL + 0, FL + 0, FL + 1, FL + 1};
    int* LAY = FL + 2;

    // Resolve layout + pair order on device.
    resolve_kernel<<<1, 1024>>>(eptr[0], eptr[3], eptr[4]);

    auto gemm = [](const float* A, int lda, const float* W, int ldw, const float* B,
                   float* C, int ldc, int M, int N, int K, int geluA, int reluO,
                   const float* resid, const float* skp) {
        dim3 grid(N / 64, (M + 63) / 64);
        gemm_kernel<<<grid, 256>>>(A, lda, W, ldw, B, C, ldc, M, K, geluA, reluO, resid, skp);
    };

    // ---- input projections: X = relu(x @ lin_w + lin_b) ----
    for (int t = 0; t < 3; t++)
        gemm(x_in[t], idim[t], lin_w[t], 128, lin_b[t],
             X + (size_t)roff[t] * 128, 128, ntyp[t], 128, idim[t], 0, 1, nullptr, nullptr);

    for (int li = 0; li < 2; li++) {
        const int H = li ? 4 : 8;
        const int fout = H * 16;
        const float* Xin = li ? Y : X;
        float* kqvout[3] = {Kb, Qb, Vb};

        // kqv projections (split into k|q|v column slices)
        for (int t = 0; t < 3; t++)
            for (int p = 0; p < 3; p++)
                gemm(Xin + (size_t)roff[t] * 128, 128,
                     kqv_w[li] + (size_t)t * 128 * 3 * fout + p * fout, 3 * fout,
                     kqv_b[li] + t * 3 * fout + p * fout,
                     kqvout[p] + (size_t)roff[t] * fout, fout,
                     ntyp[t], fout, 128, 0, 0, nullptr, nullptr);

        // init segment buffers
        {
            int nMH = NTOT * H, nA = NTOT * fout;
            init_kernel<<<(nA + 255) / 256, 256>>>(Mb, Db, AG, nMH, nA);
        }

        // per-edge-type relation transforms over source nodes
        for (int e = 0; e < 5; e++) {
            int ns = ntyp[esrc[e]];
            int tot = ns * fout;
            size_t shb = (size_t)2 * H * 256 * sizeof(float);
            relx_kernel<<<(tot + 255) / 256, 256, shb>>>(
                Kb + (size_t)roff[esrc[e]] * fout, Vb + (size_t)roff[esrc[e]] * fout,
                krel[li] + e * H * 256, vrel[li] + e * H * 256,
                KR + (size_t)kroff[e] * fout, VR + (size_t)kroff[e] * fout, ns, H);
        }

        // scores + segment max
        for (int e = 0; e < 5; e++) {
            int tot = ecnt[e] * H;
            score_kernel<<<(tot + 255) / 256, 256>>>(
                epri[e], ealt[e], eflag[e], LAY,
                Qb + (size_t)roff[edst[e]] * fout, KR + (size_t)kroff[e] * fout,
                prel[li] + e * H, SCb + (size_t)scoff[e] * H,
                Mb + (size_t)roff[edst[e]] * H, ecnt[e], H,
                ntyp[esrc[e]], ntyp[edst[e]]);
        }
        // exp + segment sum
        for (int e = 0; e < 5; e++) {
            int tot = ecnt[e] * H;
            expsum_kernel<<<(tot + 255) / 256, 256>>>(
                epri[e], ealt[e], eflag[e], LAY,
                Mb + (size_t)roff[edst[e]] * H,
                SCb + (size_t)scoff[e] * H, Db + (size_t)roff[edst[e]] * H,
                ecnt[e], H, ntyp[edst[e]]);
        }
        // weighted message aggregation
        for (int e = 0; e < 5; e++) {
            int tot = ecnt[e] * (fout / 4);
            agg_kernel<<<(tot + 255) / 256, 256>>>(
                epri[e], ealt[e], eflag[e], LAY,
                VR + (size_t)kroff[e] * fout,
                SCb + (size_t)scoff[e] * H, Db + (size_t)roff[edst[e]] * H,
                AG + (size_t)roff[edst[e]] * fout, ecnt[e], H,
                ntyp[esrc[e]], ntyp[edst[e]]);
        }

        // output projection: gelu(agg) @ out_w + out_b (+ sigmoid-skip on layer 1)
        for (int t = 0; t < 3; t++) {
            if (li == 0) {
                gemm(AG + (size_t)roff[t] * 128, 128, outw[0] + (size_t)t * 128 * 128, 128,
                     outb[0] + t * 128, Y + (size_t)roff[t] * 128, 128,
                     ntyp[t], 128, 128, 1, 0, Xin + (size_t)roff[t] * 128, skipv[0] + t);
            } else {
                const size_t ooff[3] = {0, (size_t)NPAPER * 64, (size_t)(NPAPER + NAUTH) * 64};
                const long long need[3] = {6400000LL, 9600000LL, 9920000LL};
                if ((long long)out_size >= need[t]) {
                    gemm(AG + (size_t)roff[t] * 64, 64,
                         outw[1] + (size_t)t * 64 * 64, 64,
                         outb[1] + t * 64, (float*)d_out + ooff[t], 64,
                         ntyp[t], 64, 64, 1, 0, nullptr, nullptr);
                }
            }
        }
    }
}